// round 11
// baseline (speedup 1.0000x reference)
#include <cuda_runtime.h>
#include <cstdint>

#define NBS 100000
#define NGS 20000
#define EL  1000000
#define EX  200000
#define CAP 64

#define TM 256
#define BUSB ((NBS + TM - 1) / TM)   // 391
#define GENB ((NGS + TM - 1) / TM)   // 79

#define XS2 260                       // u64 stride per k-row of duplicated x

// ---------------- scratch (static device globals; no allocation) ----------------
__device__ float g_hb[NBS * 64];
__device__ float g_hg[NGS * 64];
__device__ float g_aggL[NBS * 64];   // mean of hb over line edges, at bus dst
__device__ float g_aggG[NBS * 64];   // mean of hg over g2b edges, at bus dst
__device__ float g_aggB[NGS * 64];   // mean of hb over b2g edges, at gen dst
__device__ int   g_cntL[NBS], g_cntG[NBS], g_cntB[NGS];
__device__ int   g_csrL[(size_t)NBS * CAP];
__device__ int   g_csrG[(size_t)NBS * CAP];
__device__ int   g_csrB[(size_t)NGS * CAP];
__device__ float g_pool[128];

// ---------------- f32x2 helpers ----------------
__device__ __forceinline__ unsigned long long packf2(float v) {
    unsigned long long r;
    asm("mov.b64 %0, {%1, %1};" : "=l"(r) : "f"(v));
    return r;
}
__device__ __forceinline__ unsigned long long packf2b(float a, float b) {
    unsigned long long r;
    asm("mov.b64 %0, {%1, %2};" : "=l"(r) : "f"(a), "f"(b));
    return r;
}
__device__ __forceinline__ void fma2(unsigned long long& acc,
                                     unsigned long long a, unsigned long long b) {
    asm("fma.rn.f32x2 %0, %1, %2, %0;" : "+l"(acc) : "l"(a), "l"(b));
}
__device__ __forceinline__ void lds2u64(unsigned long long& a, unsigned long long& b,
                                        const void* p) {
    asm volatile("ld.shared.v2.u64 {%0, %1}, [%2];"
                 : "=l"(a), "=l"(b) : "l"(__cvta_generic_to_shared(p)));
}
__device__ __forceinline__ void sts64(void* p, unsigned long long v) {
    asm volatile("st.shared.u64 [%0], %1;"
                 :: "l"(__cvta_generic_to_shared(p)), "l"(v) : "memory");
}
__device__ __forceinline__ void unpackf2(unsigned long long v, float& a, float& b) {
    asm("mov.b64 {%0, %1}, %2;" : "=f"(a), "=f"(b) : "l"(v));
}

// ---------------- CSR build (cnt arrays zero at module load and re-zeroed by
// k_pool_all each call -> graph replays stay correct) ----------------
__global__ void k_fill_line(const int* __restrict__ ls, const int* __restrict__ ldst)
{
    int i = blockIdx.x * blockDim.x + threadIdx.x;
    if (i < EL) {
        int d = __ldg(&ldst[i]);
        int pos = atomicAdd(&g_cntL[d], 1);
        if (pos < CAP) g_csrL[(size_t)d * CAP + pos] = __ldg(&ls[i]);
    }
}
__global__ void k_fill_x(const int* __restrict__ gs, const int* __restrict__ gd,
                         const int* __restrict__ bs, const int* __restrict__ bd)
{
    int i = blockIdx.x * blockDim.x + threadIdx.x;
    if (i < EX) {
        int d = __ldg(&gd[i]);
        int pos = atomicAdd(&g_cntG[d], 1);
        if (pos < CAP) g_csrG[(size_t)d * CAP + pos] = __ldg(&gs[i]);
        int d2 = __ldg(&bd[i]);
        int pos2 = atomicAdd(&g_cntB[d2], 1);
        if (pos2 < CAP) g_csrB[(size_t)d2 * CAP + pos2] = __ldg(&bs[i]);
    }
}

// ---------------- pull-mode aggregation (all 3 edge types, writes MEANS) --------
__global__ void __launch_bounds__(256) k_gather(const float* hb, const float* hg)
{
    int tid = blockIdx.x * 256 + threadIdx.x;
    int node = tid >> 4;
    int q = tid & 15;

    const float4* hsrc;
    const int* bucket;
    float4* aggout;
    int deg;
    const float* hbp = hb ? hb : (const float*)g_hb;
    const float* hgp = hg ? hg : (const float*)g_hg;

    if (node < NBS) {
        deg = g_cntL[node];
        bucket = g_csrL + (size_t)node * CAP;
        hsrc = (const float4*)hbp;
        aggout = (float4*)g_aggL + (size_t)node * 16;
    } else if (node < 2 * NBS) {
        int m = node - NBS;
        deg = g_cntG[m];
        bucket = g_csrG + (size_t)m * CAP;
        hsrc = (const float4*)hgp;
        aggout = (float4*)g_aggG + (size_t)m * 16;
    } else if (node < 2 * NBS + NGS) {
        int m = node - 2 * NBS;
        deg = g_cntB[m];
        bucket = g_csrB + (size_t)m * CAP;
        hsrc = (const float4*)hbp;
        aggout = (float4*)g_aggB + (size_t)m * 16;
    } else return;

    if (deg > CAP) deg = CAP;
    float4 acc = make_float4(0.f, 0.f, 0.f, 0.f);
#pragma unroll 4
    for (int e = 0; e < deg; e++) {
        int s = __ldg(&bucket[e]);
        float4 v = __ldg(&hsrc[(size_t)s * 16 + q]);
        acc.x += v.x; acc.y += v.y; acc.z += v.z; acc.w += v.w;
    }
    float inv = 1.f / (float)max(deg, 1);
    acc.x *= inv; acc.y *= inv; acc.z *= inv; acc.w *= inv;
    aggout[q] = acc;
}

// ---------------- register-tiled fused update (bus + gen) ----------------
// bus: new_hb = relu(hb@Wsb + mL@Wl + mG@Wg2b + bsb), K=192
// gen: new_hg = relu(hg@Wsg + mB@Wb2g + bsg),         K=128
// 256 rows x 64 cols per block; thread owns 8 rows x 8 cols as 2x2 quads:
// rows {tr*4..+4, 128+tr*4..+4}, cols {tc*4..+4, 32+tc*4..+4}. Every LDS
// instruction's warp-unique addresses span one contiguous 128B line.
// Inner loop: 6 LDS.v2.u64 + 32 FFMA2 per k -> fma-pipe-bound.
__global__ void __launch_bounds__(256, 2) k_fused(
    const float* hbin, const float* hgin,
    const float* __restrict__ Wsb, const float* __restrict__ Wl,
    const float* __restrict__ Wg2b, const float* __restrict__ bsb,
    const float* __restrict__ Wsg, const float* __restrict__ Wb2g,
    const float* __restrict__ bsg)
{
    extern __shared__ float sm[];
    float* sW = sm;                                   // [<=192*64]
    float* sB = sm + 12288;                           // [64]
    unsigned long long* sX =
        (unsigned long long*)(sm + 12288 + 64);       // [16][XS2] u64 (x duplicated)

    int t = threadIdx.x;
    bool bus = blockIdx.x < BUSB;

    if (bus) {
        for (int idx = t; idx < 4096; idx += 256) {
            sW[idx]        = Wsb[idx];
            sW[4096 + idx] = Wl[idx];
            sW[8192 + idx] = Wg2b[idx];
        }
        if (t < 64) sB[t] = bsb[t];
    } else {
        for (int idx = t; idx < 4096; idx += 256) {
            sW[idx]        = Wsg[idx];
            sW[4096 + idx] = Wb2g[idx];
        }
        if (t < 64) sB[t] = bsg[t];
    }

    int tile = bus ? blockIdx.x : blockIdx.x - BUSB;
    int n    = bus ? NBS : NGS;
    int row0 = tile * TM;
    const float* hsrc = bus ? (hbin ? hbin : (const float*)g_hb)
                            : (hgin ? hgin : (const float*)g_hg);
    const float* agg1 = bus ? g_aggL : g_aggB;
    int nkc = bus ? 12 : 8;      // chunks of 16 k

    // staging: thread stages its own row (row0 + t) for the 16-k chunk
    int gr = min(row0 + t, n - 1);

    // compute ids
    int tc = t & 7;              // col quad base: cols tc*4 and 32+tc*4
    int tr = t >> 3;             // row quad base: rows tr*4 and 128+tr*4

    __syncthreads();   // sW/sB visible

    unsigned long long acc[32];  // [rIdx 0..7][cPair 0..3]
    {
        unsigned long long bA0 = packf2b(sB[tc * 4],      sB[tc * 4 + 1]);
        unsigned long long bA1 = packf2b(sB[tc * 4 + 2],  sB[tc * 4 + 3]);
        unsigned long long bB0 = packf2b(sB[32 + tc * 4],     sB[32 + tc * 4 + 1]);
        unsigned long long bB1 = packf2b(sB[32 + tc * 4 + 2], sB[32 + tc * 4 + 3]);
#pragma unroll
        for (int r = 0; r < 8; r++) {
            acc[r * 4 + 0] = bA0; acc[r * 4 + 1] = bA1;
            acc[r * 4 + 2] = bB0; acc[r * 4 + 3] = bB1;
        }
    }

    // prefetch chunk 0 (always segment 0 = h): 16 floats of row gr
    float4 v0 = *(const float4*)(hsrc + (size_t)gr * 64 + 0);
    float4 v1 = *(const float4*)(hsrc + (size_t)gr * 64 + 4);
    float4 v2 = *(const float4*)(hsrc + (size_t)gr * 64 + 8);
    float4 v3 = *(const float4*)(hsrc + (size_t)gr * 64 + 12);

    for (int kc = 0; kc < nkc; kc++) {
        sts64(&sX[0  * XS2 + t], packf2(v0.x));
        sts64(&sX[1  * XS2 + t], packf2(v0.y));
        sts64(&sX[2  * XS2 + t], packf2(v0.z));
        sts64(&sX[3  * XS2 + t], packf2(v0.w));
        sts64(&sX[4  * XS2 + t], packf2(v1.x));
        sts64(&sX[5  * XS2 + t], packf2(v1.y));
        sts64(&sX[6  * XS2 + t], packf2(v1.z));
        sts64(&sX[7  * XS2 + t], packf2(v1.w));
        sts64(&sX[8  * XS2 + t], packf2(v2.x));
        sts64(&sX[9  * XS2 + t], packf2(v2.y));
        sts64(&sX[10 * XS2 + t], packf2(v2.z));
        sts64(&sX[11 * XS2 + t], packf2(v2.w));
        sts64(&sX[12 * XS2 + t], packf2(v3.x));
        sts64(&sX[13 * XS2 + t], packf2(v3.y));
        sts64(&sX[14 * XS2 + t], packf2(v3.z));
        sts64(&sX[15 * XS2 + t], packf2(v3.w));
        __syncthreads();

        int kc1 = kc + 1;
        if (kc1 < nkc) {   // prefetch next chunk (overlaps with compute below)
            int seg = kc1 >> 2;          // 0: h, 1: agg1, 2: aggG (bus only)
            int kk  = (kc1 & 3) * 16;
            const float* base = (seg == 0) ? hsrc : (seg == 1) ? agg1 : g_aggG;
            const float* p = base + (size_t)gr * 64 + kk;
            v0 = *(const float4*)(p + 0);
            v1 = *(const float4*)(p + 4);
            v2 = *(const float4*)(p + 8);
            v3 = *(const float4*)(p + 12);
        }

        const float* wk = sW + kc * 1024 + tc * 4;       // 16 k-rows of 64 cols
        const unsigned long long* xk = sX + tr * 4;
#pragma unroll
        for (int k = 0; k < 16; k++) {
            unsigned long long wA0, wA1, wB0, wB1;
            lds2u64(wA0, wA1, wk + k * 64);          // cols tc*4..+4
            lds2u64(wB0, wB1, wk + k * 64 + 32);     // cols 32+tc*4..+4
            unsigned long long xA0, xA1, xA2, xA3, xB0, xB1, xB2, xB3;
            lds2u64(xA0, xA1, xk + k * XS2);         // rows tr*4..+2
            lds2u64(xA2, xA3, xk + k * XS2 + 2);     // rows tr*4+2..+4
            lds2u64(xB0, xB1, xk + k * XS2 + 128);   // rows 128+tr*4..
            lds2u64(xB2, xB3, xk + k * XS2 + 130);
            fma2(acc[0],  xA0, wA0); fma2(acc[1],  xA0, wA1);
            fma2(acc[2],  xA0, wB0); fma2(acc[3],  xA0, wB1);
            fma2(acc[4],  xA1, wA0); fma2(acc[5],  xA1, wA1);
            fma2(acc[6],  xA1, wB0); fma2(acc[7],  xA1, wB1);
            fma2(acc[8],  xA2, wA0); fma2(acc[9],  xA2, wA1);
            fma2(acc[10], xA2, wB0); fma2(acc[11], xA2, wB1);
            fma2(acc[12], xA3, wA0); fma2(acc[13], xA3, wA1);
            fma2(acc[14], xA3, wB0); fma2(acc[15], xA3, wB1);
            fma2(acc[16], xB0, wA0); fma2(acc[17], xB0, wA1);
            fma2(acc[18], xB0, wB0); fma2(acc[19], xB0, wB1);
            fma2(acc[20], xB1, wA0); fma2(acc[21], xB1, wA1);
            fma2(acc[22], xB1, wB0); fma2(acc[23], xB1, wB1);
            fma2(acc[24], xB2, wA0); fma2(acc[25], xB2, wA1);
            fma2(acc[26], xB2, wB0); fma2(acc[27], xB2, wB1);
            fma2(acc[28], xB3, wA0); fma2(acc[29], xB3, wA1);
            fma2(acc[30], xB3, wB0); fma2(acc[31], xB3, wB1);
        }
        __syncthreads();   // compute done before next STS overwrites sX
    }

    // epilogue: relu + store 8 rows x (2 x float4)
    float* outp = bus ? g_hb : g_hg;
#pragma unroll
    for (int r = 0; r < 8; r++) {
        int rr = row0 + (r < 4 ? tr * 4 + r : 128 + tr * 4 + (r - 4));
        if (rr < n) {
            float4 oA, oB;
            unpackf2(acc[r * 4 + 0], oA.x, oA.y);
            unpackf2(acc[r * 4 + 1], oA.z, oA.w);
            unpackf2(acc[r * 4 + 2], oB.x, oB.y);
            unpackf2(acc[r * 4 + 3], oB.z, oB.w);
            oA.x = fmaxf(oA.x, 0.f); oA.y = fmaxf(oA.y, 0.f);
            oA.z = fmaxf(oA.z, 0.f); oA.w = fmaxf(oA.w, 0.f);
            oB.x = fmaxf(oB.x, 0.f); oB.y = fmaxf(oB.y, 0.f);
            oB.z = fmaxf(oB.z, 0.f); oB.w = fmaxf(oB.w, 0.f);
            *(float4*)(outp + (size_t)rr * 64 + tc * 4) = oA;
            *(float4*)(outp + (size_t)rr * 64 + 32 + tc * 4) = oB;
        }
    }
}

// ---------------- sum pooling (bus + gen) + cnt re-zero for next call ----------------
__global__ void k_pool_all() {
    // re-zero CSR counters (consumed this call; next call/replay needs zeros)
    for (int i = blockIdx.x * 256 + threadIdx.x; i < NBS; i += 300 * 256) {
        g_cntL[i] = 0; g_cntG[i] = 0;
        if (i < NGS) g_cntB[i] = 0;
    }

    bool bus = blockIdx.x < 240;
    const float* h = bus ? g_hb : g_hg;
    int n = bus ? NBS : NGS;
    int obase = bus ? 0 : 64;
    int bid = bus ? blockIdx.x : blockIdx.x - 240;
    int nb  = bus ? 240 : 60;

    int col = threadIdx.x & 63, grp = threadIdx.x >> 6;
    float s = 0.f;
    for (int r = bid * 4 + grp; r < n; r += nb * 4)
        s += h[(size_t)r * 64 + col];
    __shared__ float sh[256];
    sh[threadIdx.x] = s;
    __syncthreads();
    if (grp == 0)
        atomicAdd(&g_pool[obase + col],
                  sh[col] + sh[col + 64] + sh[col + 128] + sh[col + 192]);
}

// ---------------- MLP head (also re-zeroes g_pool for next call) ----------------
__global__ void k_head(const float* __restrict__ W_h, const float* __restrict__ b_h,
                       const float* __restrict__ W_o, const float* __restrict__ b_o,
                       float* __restrict__ out)
{
    __shared__ float sg[128], st[64];
    int t = threadIdx.x;   // 128 threads
    sg[t] = g_pool[t];
    __syncthreads();
    g_pool[t] = 0.f;       // consumed; restore zero-invariant for replay
    if (t < 64) {
        float a = b_h[t];
#pragma unroll
        for (int i = 0; i < 128; i++) a += sg[i] * W_h[i * 64 + t];
        st[t] = fmaxf(a, 0.f);
    }
    __syncthreads();
    if (t < 16) {
        float o = b_o[t];
#pragma unroll
        for (int j = 0; j < 64; j++) o += st[j] * W_o[j * 16 + t];
        out[t] = o;
    }
}

// ---------------- launch ----------------
extern "C" void kernel_launch(void* const* d_in, const int* in_sizes, int n_in,
                              void* d_out, int out_size)
{
    const float* x_bus   = (const float*)d_in[0];
    const float* x_gen   = (const float*)d_in[1];
    const int* line_src  = (const int*)d_in[2];
    const int* line_dst  = (const int*)d_in[3];
    const int* g2b_src   = (const int*)d_in[4];
    const int* g2b_dst   = (const int*)d_in[5];
    const int* b2g_src   = (const int*)d_in[6];
    const int* b2g_dst   = (const int*)d_in[7];
    const float* Wsb[2]  = { (const float*)d_in[8],  (const float*)d_in[15] };
    const float* Wsg[2]  = { (const float*)d_in[9],  (const float*)d_in[16] };
    const float* Wl[2]   = { (const float*)d_in[10], (const float*)d_in[17] };
    const float* Wg2b[2] = { (const float*)d_in[11], (const float*)d_in[18] };
    const float* Wb2g[2] = { (const float*)d_in[12], (const float*)d_in[19] };
    const float* bsb[2]  = { (const float*)d_in[13], (const float*)d_in[20] };
    const float* bsg[2]  = { (const float*)d_in[14], (const float*)d_in[21] };
    const float* W_h = (const float*)d_in[22];
    const float* b_h = (const float*)d_in[23];
    const float* W_o = (const float*)d_in[24];
    const float* b_o = (const float*)d_in[25];

    const int SMEM_FUSED = (12288 + 64) * 4 + 16 * XS2 * 8;   // 82688 B
    cudaFuncSetAttribute(k_fused, cudaFuncAttributeMaxDynamicSharedMemorySize,
                         SMEM_FUSED);

    const int GATH_BLOCKS = ((2 * NBS + NGS) * 16 + 255) / 256;  // 13750

    // launch order chosen so launch #4 (= the ncu capture slot) is k_fused
    k_fill_line<<<(EL + 255) / 256, 256>>>(line_src, line_dst);           // 1
    k_fill_x<<<(EX + 255) / 256, 256>>>(g2b_src, g2b_dst,                 // 2
                                        b2g_src, b2g_dst);
    k_gather<<<GATH_BLOCKS, 256>>>(x_bus, x_gen);                         // 3
    k_fused<<<BUSB + GENB, 256, SMEM_FUSED>>>(x_bus, x_gen,               // 4 (ncu)
                                  Wsb[0], Wl[0], Wg2b[0], bsb[0],
                                  Wsg[0], Wb2g[0], bsg[0]);
    k_gather<<<GATH_BLOCKS, 256>>>(nullptr, nullptr);                     // 5
    k_fused<<<BUSB + GENB, 256, SMEM_FUSED>>>(nullptr, nullptr,           // 6
                                  Wsb[1], Wl[1], Wg2b[1], bsb[1],
                                  Wsg[1], Wb2g[1], bsg[1]);
    k_pool_all<<<300, 256>>>();                                           // 7
    k_head<<<1, 128>>>(W_h, b_h, W_o, b_o, (float*)d_out);                // 8
}

// round 12
// speedup vs baseline: 1.0253x; 1.0253x over previous
#include <cuda_runtime.h>
#include <cstdint>

#define NBS 100000
#define NGS 20000
#define EL  1000000
#define EX  200000
#define CAP 64

#define TM 192
#define BUSB ((NBS + TM - 1) / TM)   // 521
#define GENB ((NGS + TM - 1) / TM)   // 105

#define XSTRF 196                     // float stride per k-row of natural x tile

// ---------------- scratch (static device globals; no allocation) ----------------
__device__ float g_hb[NBS * 64];
__device__ float g_hg[NGS * 64];
__device__ float g_aggL[NBS * 64];   // mean of hb over line edges, at bus dst
__device__ float g_aggG[NBS * 64];   // mean of hg over g2b edges, at bus dst
__device__ float g_aggB[NGS * 64];   // mean of hb over b2g edges, at gen dst
__device__ int   g_cntL[NBS], g_cntG[NBS], g_cntB[NGS];
__device__ int   g_csrL[(size_t)NBS * CAP];
__device__ int   g_csrG[(size_t)NBS * CAP];
__device__ int   g_csrB[(size_t)NGS * CAP];
__device__ float g_pool[128];

// ---------------- f32x2 helpers ----------------
__device__ __forceinline__ unsigned long long packf2(float v) {
    unsigned long long r;
    asm("mov.b64 %0, {%1, %1};" : "=l"(r) : "f"(v));
    return r;
}
__device__ __forceinline__ void fma2(unsigned long long& acc,
                                     unsigned long long a, unsigned long long b) {
    asm("fma.rn.f32x2 %0, %1, %2, %0;" : "+l"(acc) : "l"(a), "l"(b));
}
__device__ __forceinline__ void lds2u64(unsigned long long& a, unsigned long long& b,
                                        const void* p) {
    asm volatile("ld.shared.v2.u64 {%0, %1}, [%2];"
                 : "=l"(a), "=l"(b) : "l"(__cvta_generic_to_shared(p)));
}
__device__ __forceinline__ void unpackf2(unsigned long long v, float& a, float& b) {
    asm("mov.b64 {%0, %1}, %2;" : "=f"(a), "=f"(b) : "l"(v));
}

// ---------------- CSR build (cnt arrays zero at module load and re-zeroed by
// k_pool_all each call -> graph replays stay correct) ----------------
__global__ void k_fill_line(const int* __restrict__ ls, const int* __restrict__ ldst)
{
    int i = blockIdx.x * blockDim.x + threadIdx.x;
    if (i < EL) {
        int d = __ldg(&ldst[i]);
        int pos = atomicAdd(&g_cntL[d], 1);
        if (pos < CAP) g_csrL[(size_t)d * CAP + pos] = __ldg(&ls[i]);
    }
}
__global__ void k_fill_x(const int* __restrict__ gs, const int* __restrict__ gd,
                         const int* __restrict__ bs, const int* __restrict__ bd)
{
    int i = blockIdx.x * blockDim.x + threadIdx.x;
    if (i < EX) {
        int d = __ldg(&gd[i]);
        int pos = atomicAdd(&g_cntG[d], 1);
        if (pos < CAP) g_csrG[(size_t)d * CAP + pos] = __ldg(&gs[i]);
        int d2 = __ldg(&bd[i]);
        int pos2 = atomicAdd(&g_cntB[d2], 1);
        if (pos2 < CAP) g_csrB[(size_t)d2 * CAP + pos2] = __ldg(&bs[i]);
    }
}

// ---------------- pull-mode aggregation (all 3 edge types, writes MEANS) --------
__global__ void __launch_bounds__(256) k_gather(const float* hb, const float* hg)
{
    int tid = blockIdx.x * 256 + threadIdx.x;
    int node = tid >> 4;
    int q = tid & 15;

    const float4* hsrc;
    const int* bucket;
    float4* aggout;
    int deg;
    const float* hbp = hb ? hb : (const float*)g_hb;
    const float* hgp = hg ? hg : (const float*)g_hg;

    if (node < NBS) {
        deg = g_cntL[node];
        bucket = g_csrL + (size_t)node * CAP;
        hsrc = (const float4*)hbp;
        aggout = (float4*)g_aggL + (size_t)node * 16;
    } else if (node < 2 * NBS) {
        int m = node - NBS;
        deg = g_cntG[m];
        bucket = g_csrG + (size_t)m * CAP;
        hsrc = (const float4*)hgp;
        aggout = (float4*)g_aggG + (size_t)m * 16;
    } else if (node < 2 * NBS + NGS) {
        int m = node - 2 * NBS;
        deg = g_cntB[m];
        bucket = g_csrB + (size_t)m * CAP;
        hsrc = (const float4*)hbp;
        aggout = (float4*)g_aggB + (size_t)m * 16;
    } else return;

    if (deg > CAP) deg = CAP;
    float4 acc = make_float4(0.f, 0.f, 0.f, 0.f);
#pragma unroll 4
    for (int e = 0; e < deg; e++) {
        int s = __ldg(&bucket[e]);
        float4 v = __ldg(&hsrc[(size_t)s * 16 + q]);
        acc.x += v.x; acc.y += v.y; acc.z += v.z; acc.w += v.w;
    }
    float inv = 1.f / (float)max(deg, 1);
    acc.x *= inv; acc.y *= inv; acc.z *= inv; acc.w *= inv;
    aggout[q] = acc;
}

// ---------------- register-tiled fused update (bus + gen) ----------------
// bus: new_hb = relu(hb@Wsb + mL@Wl + mG@Wg2b + bsb), K=192
// gen: new_hg = relu(hg@Wsg + mB@Wb2g + bsg),         K=128
// ROW-PAIR f32x2 scheme: x tile natural [k][row] fp32 (no duplication);
// ld.shared.v2.u64 yields consecutive-row pairs; weights duplicated {w,w} at
// pack time (4 packf2/k, reused across 12 rows). Thread = 12 rows x 4 cols
// (24 u64 acc). Per k: 1 w-LDS.128 + 3 x-LDS.v2.u64 + 4 pack + 24 FFMA2.
__global__ void __launch_bounds__(256, 3) k_fused(
    const float* hbin, const float* hgin,
    const float* __restrict__ Wsb, const float* __restrict__ Wl,
    const float* __restrict__ Wg2b, const float* __restrict__ bsb,
    const float* __restrict__ Wsg, const float* __restrict__ Wb2g,
    const float* __restrict__ bsg)
{
    extern __shared__ float sm[];
    float* sW = sm;                     // [<=192*64]
    float* sB = sm + 12288;             // [64]
    float* sX = sm + 12288 + 64;        // [16][XSTRF] natural fp32 x tile

    int t = threadIdx.x;
    bool bus = blockIdx.x < BUSB;

    if (bus) {
        for (int idx = t; idx < 4096; idx += 256) {
            sW[idx]        = Wsb[idx];
            sW[4096 + idx] = Wl[idx];
            sW[8192 + idx] = Wg2b[idx];
        }
        if (t < 64) sB[t] = bsb[t];
    } else {
        for (int idx = t; idx < 4096; idx += 256) {
            sW[idx]        = Wsg[idx];
            sW[4096 + idx] = Wb2g[idx];
        }
        if (t < 64) sB[t] = bsg[t];
    }

    int tile = bus ? blockIdx.x : blockIdx.x - BUSB;
    int n    = bus ? NBS : NGS;
    int row0 = tile * TM;
    const float* hsrc = bus ? (hbin ? hbin : (const float*)g_hb)
                            : (hgin ? hgin : (const float*)g_hg);
    const float* agg1 = bus ? g_aggL : g_aggB;
    int nkc = bus ? 12 : 8;      // chunks of 16 k

    // staging: thread t (<192) stages row row0+t of the current 16-k chunk
    int gr = min(row0 + t, n - 1);

    // compute ids: thread owns rows [rbase, rbase+12), cols [tc*4, tc*4+4)
    int tc = t & 15;
    int rbase = (t >> 4) * 12;

    // acc[rp*4+c] holds {out[rbase+2rp][tc*4+c], out[rbase+2rp+1][tc*4+c]}
    unsigned long long acc[24];
    {
        // sW/sB not yet guaranteed visible; bias read after first sync below.
        // Initialize after sync instead.
    }

    __syncthreads();   // sW/sB visible

#pragma unroll
    for (int rp = 0; rp < 6; rp++) {
#pragma unroll
        for (int c = 0; c < 4; c++) acc[rp * 4 + c] = packf2(sB[tc * 4 + c]);
    }

    for (int kc = 0; kc < nkc; kc++) {
        if (kc > 0) __syncthreads();   // previous compute done; sX reusable
        if (t < TM) {
            int seg = kc >> 2;          // 0: h, 1: agg1, 2: aggG (bus only)
            int kk  = (kc & 3) * 16;
            const float* base = (seg == 0) ? hsrc : (seg == 1) ? agg1 : g_aggG;
            const float* p = base + (size_t)gr * 64 + kk;
            float4 v0 = *(const float4*)(p + 0);
            float4 v1 = *(const float4*)(p + 4);
            float4 v2 = *(const float4*)(p + 8);
            float4 v3 = *(const float4*)(p + 12);
            sX[0  * XSTRF + t] = v0.x;  sX[1  * XSTRF + t] = v0.y;
            sX[2  * XSTRF + t] = v0.z;  sX[3  * XSTRF + t] = v0.w;
            sX[4  * XSTRF + t] = v1.x;  sX[5  * XSTRF + t] = v1.y;
            sX[6  * XSTRF + t] = v1.z;  sX[7  * XSTRF + t] = v1.w;
            sX[8  * XSTRF + t] = v2.x;  sX[9  * XSTRF + t] = v2.y;
            sX[10 * XSTRF + t] = v2.z;  sX[11 * XSTRF + t] = v2.w;
            sX[12 * XSTRF + t] = v3.x;  sX[13 * XSTRF + t] = v3.y;
            sX[14 * XSTRF + t] = v3.z;  sX[15 * XSTRF + t] = v3.w;
        }
        __syncthreads();   // sX ready

        const float* wbase = sW + kc * 1024 + tc * 4;
#pragma unroll
        for (int k = 0; k < 16; k++) {
            float4 w = *(const float4*)(wbase + k * 64);
            unsigned long long wd0 = packf2(w.x);
            unsigned long long wd1 = packf2(w.y);
            unsigned long long wd2 = packf2(w.z);
            unsigned long long wd3 = packf2(w.w);
            const void* xp = sX + k * XSTRF + rbase;
            unsigned long long x0, x1, x2, x3, x4, x5;
            lds2u64(x0, x1, xp);                                   // rows +0..3
            lds2u64(x2, x3, (const char*)xp + 16);                 // rows +4..7
            lds2u64(x4, x5, (const char*)xp + 32);                 // rows +8..11
            fma2(acc[0],  x0, wd0); fma2(acc[1],  x0, wd1);
            fma2(acc[2],  x0, wd2); fma2(acc[3],  x0, wd3);
            fma2(acc[4],  x1, wd0); fma2(acc[5],  x1, wd1);
            fma2(acc[6],  x1, wd2); fma2(acc[7],  x1, wd3);
            fma2(acc[8],  x2, wd0); fma2(acc[9],  x2, wd1);
            fma2(acc[10], x2, wd2); fma2(acc[11], x2, wd3);
            fma2(acc[12], x3, wd0); fma2(acc[13], x3, wd1);
            fma2(acc[14], x3, wd2); fma2(acc[15], x3, wd3);
            fma2(acc[16], x4, wd0); fma2(acc[17], x4, wd1);
            fma2(acc[18], x4, wd2); fma2(acc[19], x4, wd3);
            fma2(acc[20], x5, wd0); fma2(acc[21], x5, wd1);
            fma2(acc[22], x5, wd2); fma2(acc[23], x5, wd3);
        }
    }

    // epilogue: relu + store (12 rows x 4 cols)
    float* outp = bus ? g_hb : g_hg;
#pragma unroll
    for (int rp = 0; rp < 6; rp++) {
        int rr0 = row0 + rbase + 2 * rp;
        float4 o0, o1;
        unpackf2(acc[rp * 4 + 0], o0.x, o1.x);
        unpackf2(acc[rp * 4 + 1], o0.y, o1.y);
        unpackf2(acc[rp * 4 + 2], o0.z, o1.z);
        unpackf2(acc[rp * 4 + 3], o0.w, o1.w);
        if (rr0 < n) {
            o0.x = fmaxf(o0.x, 0.f); o0.y = fmaxf(o0.y, 0.f);
            o0.z = fmaxf(o0.z, 0.f); o0.w = fmaxf(o0.w, 0.f);
            *(float4*)(outp + (size_t)rr0 * 64 + tc * 4) = o0;
        }
        if (rr0 + 1 < n) {
            o1.x = fmaxf(o1.x, 0.f); o1.y = fmaxf(o1.y, 0.f);
            o1.z = fmaxf(o1.z, 0.f); o1.w = fmaxf(o1.w, 0.f);
            *(float4*)(outp + (size_t)(rr0 + 1) * 64 + tc * 4) = o1;
        }
    }
}

// ---------------- sum pooling (bus + gen) + cnt re-zero for next call ----------------
__global__ void k_pool_all() {
    // re-zero CSR counters (consumed this call; next call/replay needs zeros)
    for (int i = blockIdx.x * 256 + threadIdx.x; i < NBS; i += 300 * 256) {
        g_cntL[i] = 0; g_cntG[i] = 0;
        if (i < NGS) g_cntB[i] = 0;
    }

    bool bus = blockIdx.x < 240;
    const float* h = bus ? g_hb : g_hg;
    int n = bus ? NBS : NGS;
    int obase = bus ? 0 : 64;
    int bid = bus ? blockIdx.x : blockIdx.x - 240;
    int nb  = bus ? 240 : 60;

    int col = threadIdx.x & 63, grp = threadIdx.x >> 6;
    float s = 0.f;
    for (int r = bid * 4 + grp; r < n; r += nb * 4)
        s += h[(size_t)r * 64 + col];
    __shared__ float sh[256];
    sh[threadIdx.x] = s;
    __syncthreads();
    if (grp == 0)
        atomicAdd(&g_pool[obase + col],
                  sh[col] + sh[col + 64] + sh[col + 128] + sh[col + 192]);
}

// ---------------- MLP head (also re-zeroes g_pool for next call) ----------------
__global__ void k_head(const float* __restrict__ W_h, const float* __restrict__ b_h,
                       const float* __restrict__ W_o, const float* __restrict__ b_o,
                       float* __restrict__ out)
{
    __shared__ float sg[128], st[64];
    int t = threadIdx.x;   // 128 threads
    sg[t] = g_pool[t];
    __syncthreads();
    g_pool[t] = 0.f;       // consumed; restore zero-invariant for replay
    if (t < 64) {
        float a = b_h[t];
#pragma unroll
        for (int i = 0; i < 128; i++) a += sg[i] * W_h[i * 64 + t];
        st[t] = fmaxf(a, 0.f);
    }
    __syncthreads();
    if (t < 16) {
        float o = b_o[t];
#pragma unroll
        for (int j = 0; j < 64; j++) o += st[j] * W_o[j * 16 + t];
        out[t] = o;
    }
}

// ---------------- launch ----------------
extern "C" void kernel_launch(void* const* d_in, const int* in_sizes, int n_in,
                              void* d_out, int out_size)
{
    const float* x_bus   = (const float*)d_in[0];
    const float* x_gen   = (const float*)d_in[1];
    const int* line_src  = (const int*)d_in[2];
    const int* line_dst  = (const int*)d_in[3];
    const int* g2b_src   = (const int*)d_in[4];
    const int* g2b_dst   = (const int*)d_in[5];
    const int* b2g_src   = (const int*)d_in[6];
    const int* b2g_dst   = (const int*)d_in[7];
    const float* Wsb[2]  = { (const float*)d_in[8],  (const float*)d_in[15] };
    const float* Wsg[2]  = { (const float*)d_in[9],  (const float*)d_in[16] };
    const float* Wl[2]   = { (const float*)d_in[10], (const float*)d_in[17] };
    const float* Wg2b[2] = { (const float*)d_in[11], (const float*)d_in[18] };
    const float* Wb2g[2] = { (const float*)d_in[12], (const float*)d_in[19] };
    const float* bsb[2]  = { (const float*)d_in[13], (const float*)d_in[20] };
    const float* bsg[2]  = { (const float*)d_in[14], (const float*)d_in[21] };
    const float* W_h = (const float*)d_in[22];
    const float* b_h = (const float*)d_in[23];
    const float* W_o = (const float*)d_in[24];
    const float* b_o = (const float*)d_in[25];

    const int SMEM_FUSED = (12288 + 64 + 16 * XSTRF) * 4;   // 61952 B
    cudaFuncSetAttribute(k_fused, cudaFuncAttributeMaxDynamicSharedMemorySize,
                         SMEM_FUSED);

    const int GATH_BLOCKS = ((2 * NBS + NGS) * 16 + 255) / 256;  // 13750

    // launch order chosen so launch #4 (= the ncu capture slot) is k_fused
    k_fill_line<<<(EL + 255) / 256, 256>>>(line_src, line_dst);           // 1
    k_fill_x<<<(EX + 255) / 256, 256>>>(g2b_src, g2b_dst,                 // 2
                                        b2g_src, b2g_dst);
    k_gather<<<GATH_BLOCKS, 256>>>(x_bus, x_gen);                         // 3
    k_fused<<<BUSB + GENB, 256, SMEM_FUSED>>>(x_bus, x_gen,               // 4 (ncu)
                                  Wsb[0], Wl[0], Wg2b[0], bsb[0],
                                  Wsg[0], Wb2g[0], bsg[0]);
    k_gather<<<GATH_BLOCKS, 256>>>(nullptr, nullptr);                     // 5
    k_fused<<<BUSB + GENB, 256, SMEM_FUSED>>>(nullptr, nullptr,           // 6
                                  Wsb[1], Wl[1], Wg2b[1], bsb[1],
                                  Wsg[1], Wb2g[1], bsg[1]);
    k_pool_all<<<300, 256>>>();                                           // 7
    k_head<<<1, 128>>>(W_h, b_h, W_o, b_o, (float*)d_out);                // 8
}

// round 14
// speedup vs baseline: 1.1748x; 1.1458x over previous
#include <cuda_runtime.h>
#include <cstdint>

#define NBS 100000
#define NGS 20000
#define EL  1000000
#define EX  200000
#define CAP 64

#define TM 128
#define BUSB ((NBS + TM - 1) / TM)   // 782
#define GENB ((NGS + TM - 1) / TM)   // 157

// ---------------- scratch (static device globals; no allocation) ----------------
__device__ float g_hb[NBS * 64];
__device__ float g_hg[NGS * 64];
__device__ float g_aggL[NBS * 64];   // mean of hb over line edges, at bus dst
__device__ float g_aggG[NBS * 64];   // mean of hg over g2b edges, at bus dst
__device__ float g_aggB[NGS * 64];   // mean of hb over b2g edges, at gen dst
__device__ int   g_cntL[NBS], g_cntG[NBS], g_cntB[NGS];
__device__ int   g_csrL[(size_t)NBS * CAP];
__device__ int   g_csrG[(size_t)NBS * CAP];
__device__ int   g_csrB[(size_t)NGS * CAP];
__device__ float g_pool[128];

// ---------------- f32x2 helpers ----------------
__device__ __forceinline__ unsigned long long packf2(float v) {
    unsigned long long r;
    asm("mov.b64 %0, {%1, %1};" : "=l"(r) : "f"(v));
    return r;
}
__device__ __forceinline__ unsigned long long packf2b(float a, float b) {
    unsigned long long r;
    asm("mov.b64 %0, {%1, %2};" : "=l"(r) : "f"(a), "f"(b));
    return r;
}
__device__ __forceinline__ void fma2(unsigned long long& acc,
                                     unsigned long long a, unsigned long long b) {
    asm("fma.rn.f32x2 %0, %1, %2, %0;" : "+l"(acc) : "l"(a), "l"(b));
}
__device__ __forceinline__ void lds2(unsigned long long& w0, unsigned long long& w1,
                                     unsigned addr) {
    asm volatile("ld.shared.v2.u64 {%0, %1}, [%2];"
                 : "=l"(w0), "=l"(w1) : "r"(addr));
}
__device__ __forceinline__ void sts64(void* p, unsigned long long v) {
    asm volatile("st.shared.u64 [%0], %1;"
                 :: "l"(__cvta_generic_to_shared(p)), "l"(v) : "memory");
}
__device__ __forceinline__ void unpackf2(unsigned long long v, float& a, float& b) {
    asm("mov.b64 {%0, %1}, %2;" : "=f"(a), "=f"(b) : "l"(v));
}

// ---------------- CSR build: count + fill padded buckets in one pass ----------------
// cnt arrays are zero at module load and re-zeroed by k_pool_all each call,
// so graph replays stay correct.
__global__ void k_fill(const int* __restrict__ ls, const int* __restrict__ ldst,
                       const int* __restrict__ gs, const int* __restrict__ gd,
                       const int* __restrict__ bs, const int* __restrict__ bd)
{
    int i = blockIdx.x * blockDim.x + threadIdx.x;
    if (i < EL) {
        int d = __ldg(&ldst[i]);
        int pos = atomicAdd(&g_cntL[d], 1);
        if (pos < CAP) g_csrL[(size_t)d * CAP + pos] = __ldg(&ls[i]);
    }
    if (i < EX) {
        int d = __ldg(&gd[i]);
        int pos = atomicAdd(&g_cntG[d], 1);
        if (pos < CAP) g_csrG[(size_t)d * CAP + pos] = __ldg(&gs[i]);
        int d2 = __ldg(&bd[i]);
        int pos2 = atomicAdd(&g_cntB[d2], 1);
        if (pos2 < CAP) g_csrB[(size_t)d2 * CAP + pos2] = __ldg(&bs[i]);
    }
}

// ---------------- pull-mode aggregation (all 3 edge types, writes MEANS) --------
// 16 threads/node (q = float4 slot). Bucket indices are single-use streams:
// load with .cs (evict-first) so they do not evict the hot src feature rows
// from L2 — the gather's src reads are the fat, reused stream.
__global__ void __launch_bounds__(256) k_gather(const float* hb, const float* hg)
{
    int tid = blockIdx.x * 256 + threadIdx.x;
    int node = tid >> 4;
    int q = tid & 15;

    const float4* hsrc;
    const int* bucket;
    float4* aggout;
    int deg;
    const float* hbp = hb ? hb : (const float*)g_hb;
    const float* hgp = hg ? hg : (const float*)g_hg;

    if (node < NBS) {
        deg = g_cntL[node];
        bucket = g_csrL + (size_t)node * CAP;
        hsrc = (const float4*)hbp;
        aggout = (float4*)g_aggL + (size_t)node * 16;
    } else if (node < 2 * NBS) {
        int m = node - NBS;
        deg = g_cntG[m];
        bucket = g_csrG + (size_t)m * CAP;
        hsrc = (const float4*)hgp;
        aggout = (float4*)g_aggG + (size_t)m * 16;
    } else if (node < 2 * NBS + NGS) {
        int m = node - 2 * NBS;
        deg = g_cntB[m];
        bucket = g_csrB + (size_t)m * CAP;
        hsrc = (const float4*)hbp;
        aggout = (float4*)g_aggB + (size_t)m * 16;
    } else return;

    if (deg > CAP) deg = CAP;
    float4 acc = make_float4(0.f, 0.f, 0.f, 0.f);
#pragma unroll 4
    for (int e = 0; e < deg; e++) {
        int s = __ldcs(&bucket[e]);            // streaming: evict-first
        float4 v = __ldg(&hsrc[(size_t)s * 16 + q]);
        acc.x += v.x; acc.y += v.y; acc.z += v.z; acc.w += v.w;
    }
    float inv = 1.f / (float)max(deg, 1);
    acc.x *= inv; acc.y *= inv; acc.z *= inv; acc.w *= inv;
    aggout[q] = acc;
}

// ---------------- register-tiled fused update (bus + gen) ----------------
// bus: new_hb = relu(hb@Wsb + mL@Wl + mG@Wg2b + bsb), K=192
// gen: new_hg = relu(hg@Wsg + mB@Wb2g + bsg),         K=128
// Tile: 128 rows x 64 cols per block of 256 threads; each thread owns an
// 8-row x 4-col register tile (16 u64 f32x2 accumulators).
// Per k: 3x lds128 feed 16 FFMA2. x-chunks ([16 k][132 rows]) double-buffered
// with global prefetch overlapping compute. (agg holds MEANS; no scaling.)
__global__ void __launch_bounds__(256, 3) k_fused(
    const float* hbin, const float* hgin,
    const float* __restrict__ Wsb, const float* __restrict__ Wl,
    const float* __restrict__ Wg2b, const float* __restrict__ bsb,
    const float* __restrict__ Wsg, const float* __restrict__ Wb2g,
    const float* __restrict__ bsg)
{
    extern __shared__ float sm[];
    float* sW = sm;                 // [<=192*64]
    float* sB = sm + 12288;         // [64]
    float* sX = sm + 12288 + 64;    // [2][16][132]

    int t = threadIdx.x;
    bool bus = blockIdx.x < BUSB;

    if (bus) {
        for (int idx = t; idx < 4096; idx += 256) {
            sW[idx]        = Wsb[idx];
            sW[4096 + idx] = Wl[idx];
            sW[8192 + idx] = Wg2b[idx];
        }
        if (t < 64) sB[t] = bsb[t];
    } else {
        for (int idx = t; idx < 4096; idx += 256) {
            sW[idx]        = Wsg[idx];
            sW[4096 + idx] = Wb2g[idx];
        }
        if (t < 64) sB[t] = bsg[t];
    }

    int tile = bus ? blockIdx.x : blockIdx.x - BUSB;
    int n    = bus ? NBS : NGS;
    int row0 = tile * TM;
    const float* hsrc = bus ? (hbin ? hbin : (const float*)g_hb)
                            : (hgin ? hgin : (const float*)g_hg);
    const float* agg1 = bus ? g_aggL : g_aggB;
    int nkc = bus ? 12 : 8;      // chunks of 16 k

    // staging ids: thread stages rows (r_a, r_b) for float4 slot kq
    int r_a = t >> 2;            // 0..63
    int r_b = r_a + 64;          // 64..127
    int kq  = t & 3;
    int grA = min(row0 + r_a, n - 1);
    int grB = min(row0 + r_b, n - 1);

    // compute ids: thread owns rows [tr*8, tr*8+8), cols [tc*4, tc*4+4)
    int tc = t & 15;
    int tr = t >> 4;

    __syncthreads();   // sW/sB visible

    unsigned long long bias0 = packf2b(sB[tc * 4],     sB[tc * 4 + 1]);
    unsigned long long bias1 = packf2b(sB[tc * 4 + 2], sB[tc * 4 + 3]);
    unsigned long long acc[16];
#pragma unroll
    for (int r = 0; r < 8; r++) { acc[2 * r] = bias0; acc[2 * r + 1] = bias1; }

    // prefetch chunk 0 (always segment 0 = h)
    float4 va = *(const float4*)(hsrc + (size_t)grA * 64 + kq * 4);
    float4 vb = *(const float4*)(hsrc + (size_t)grB * 64 + kq * 4);

    for (int kc = 0; kc < nkc; kc++) {
        float* xb = sX + (kc & 1) * 2112;
        xb[(kq * 4 + 0) * 132 + r_a] = va.x;
        xb[(kq * 4 + 1) * 132 + r_a] = va.y;
        xb[(kq * 4 + 2) * 132 + r_a] = va.z;
        xb[(kq * 4 + 3) * 132 + r_a] = va.w;
        xb[(kq * 4 + 0) * 132 + r_b] = vb.x;
        xb[(kq * 4 + 1) * 132 + r_b] = vb.y;
        xb[(kq * 4 + 2) * 132 + r_b] = vb.z;
        xb[(kq * 4 + 3) * 132 + r_b] = vb.w;
        __syncthreads();

        int kc1 = kc + 1;
        if (kc1 < nkc) {   // prefetch next chunk (overlaps with compute below)
            int seg = kc1 >> 2;          // 0: h, 1: agg1, 2: aggG (bus only)
            int kk  = (kc1 & 3) * 16 + kq * 4;
            const float* base = (seg == 0) ? hsrc : (seg == 1) ? agg1 : g_aggG;
            va = *(const float4*)(base + (size_t)grA * 64 + kk);
            vb = *(const float4*)(base + (size_t)grB * 64 + kk);
        }

        const float* wk = sW + kc * 1024 + tc * 4;   // 16 k-rows of 64 cols
        const float* xk = xb + tr * 8;
#pragma unroll
        for (int k = 0; k < 16; k++) {
            float4 w  = *(const float4*)(wk + k * 64);
            float4 x0 = *(const float4*)(xk + k * 132);
            float4 x1 = *(const float4*)(xk + k * 132 + 4);
            unsigned long long w01 = packf2b(w.x, w.y);
            unsigned long long w23 = packf2b(w.z, w.w);
            unsigned long long xx;
            xx = packf2(x0.x); fma2(acc[0],  xx, w01); fma2(acc[1],  xx, w23);
            xx = packf2(x0.y); fma2(acc[2],  xx, w01); fma2(acc[3],  xx, w23);
            xx = packf2(x0.z); fma2(acc[4],  xx, w01); fma2(acc[5],  xx, w23);
            xx = packf2(x0.w); fma2(acc[6],  xx, w01); fma2(acc[7],  xx, w23);
            xx = packf2(x1.x); fma2(acc[8],  xx, w01); fma2(acc[9],  xx, w23);
            xx = packf2(x1.y); fma2(acc[10], xx, w01); fma2(acc[11], xx, w23);
            xx = packf2(x1.z); fma2(acc[12], xx, w01); fma2(acc[13], xx, w23);
            xx = packf2(x1.w); fma2(acc[14], xx, w01); fma2(acc[15], xx, w23);
        }
        // single sync per iter is safe: next iter's STS targets the other buffer
    }

    // epilogue: relu + store 8x4 tile
    float* outp = bus ? g_hb : g_hg;
#pragma unroll
    for (int r = 0; r < 8; r++) {
        int rr = row0 + tr * 8 + r;
        if (rr < n) {
            float4 o;
            unpackf2(acc[2 * r],     o.x, o.y);
            unpackf2(acc[2 * r + 1], o.z, o.w);
            o.x = fmaxf(o.x, 0.f); o.y = fmaxf(o.y, 0.f);
            o.z = fmaxf(o.z, 0.f); o.w = fmaxf(o.w, 0.f);
            *(float4*)(outp + (size_t)rr * 64 + tc * 4) = o;
        }
    }
}

// ---------------- sum pooling (bus + gen) + cnt re-zero for next call ----------------
__global__ void k_pool_all() {
    // re-zero CSR counters (consumed this call; next call/replay needs zeros)
    for (int i = blockIdx.x * 256 + threadIdx.x; i < NBS; i += 300 * 256) {
        g_cntL[i] = 0; g_cntG[i] = 0;
        if (i < NGS) g_cntB[i] = 0;
    }

    bool bus = blockIdx.x < 240;
    const float* h = bus ? g_hb : g_hg;
    int n = bus ? NBS : NGS;
    int obase = bus ? 0 : 64;
    int bid = bus ? blockIdx.x : blockIdx.x - 240;
    int nb  = bus ? 240 : 60;

    int col = threadIdx.x & 63, grp = threadIdx.x >> 6;
    float s = 0.f;
    for (int r = bid * 4 + grp; r < n; r += nb * 4)
        s += h[(size_t)r * 64 + col];
    __shared__ float sh[256];
    sh[threadIdx.x] = s;
    __syncthreads();
    if (grp == 0)
        atomicAdd(&g_pool[obase + col],
                  sh[col] + sh[col + 64] + sh[col + 128] + sh[col + 192]);
}

// ---------------- MLP head (also re-zeroes g_pool for next call) ----------------
__global__ void k_head(const float* __restrict__ W_h, const float* __restrict__ b_h,
                       const float* __restrict__ W_o, const float* __restrict__ b_o,
                       float* __restrict__ out)
{
    __shared__ float sg[128], st[64];
    int t = threadIdx.x;   // 128 threads
    sg[t] = g_pool[t];
    __syncthreads();
    g_pool[t] = 0.f;       // consumed; restore zero-invariant for replay
    if (t < 64) {
        float a = b_h[t];
#pragma unroll
        for (int i = 0; i < 128; i++) a += sg[i] * W_h[i * 64 + t];
        st[t] = fmaxf(a, 0.f);
    }
    __syncthreads();
    if (t < 16) {
        float o = b_o[t];
#pragma unroll
        for (int j = 0; j < 64; j++) o += st[j] * W_o[j * 16 + t];
        out[t] = o;
    }
}

// ---------------- launch ----------------
extern "C" void kernel_launch(void* const* d_in, const int* in_sizes, int n_in,
                              void* d_out, int out_size)
{
    const float* x_bus   = (const float*)d_in[0];
    const float* x_gen   = (const float*)d_in[1];
    const int* line_src  = (const int*)d_in[2];
    const int* line_dst  = (const int*)d_in[3];
    const int* g2b_src   = (const int*)d_in[4];
    const int* g2b_dst   = (const int*)d_in[5];
    const int* b2g_src   = (const int*)d_in[6];
    const int* b2g_dst   = (const int*)d_in[7];
    const float* Wsb[2]  = { (const float*)d_in[8],  (const float*)d_in[15] };
    const float* Wsg[2]  = { (const float*)d_in[9],  (const float*)d_in[16] };
    const float* Wl[2]   = { (const float*)d_in[10], (const float*)d_in[17] };
    const float* Wg2b[2] = { (const float*)d_in[11], (const float*)d_in[18] };
    const float* Wb2g[2] = { (const float*)d_in[12], (const float*)d_in[19] };
    const float* bsb[2]  = { (const float*)d_in[13], (const float*)d_in[20] };
    const float* bsg[2]  = { (const float*)d_in[14], (const float*)d_in[21] };
    const float* W_h = (const float*)d_in[22];
    const float* b_h = (const float*)d_in[23];
    const float* W_o = (const float*)d_in[24];
    const float* b_o = (const float*)d_in[25];

    const int SMEM_FUSED = (12288 + 64 + 2 * 16 * 132) * 4;   // 66304 B
    cudaFuncSetAttribute(k_fused, cudaFuncAttributeMaxDynamicSharedMemorySize,
                         SMEM_FUSED);

    const int GATH_BLOCKS = ((2 * NBS + NGS) * 16 + 255) / 256;  // 13750

    // launch order chosen so launch #4 (= the ncu capture slot) is the
    // layer-2 k_gather (to verify the .cs streaming-hint DRAM% drop)
    k_fill<<<(EL + 255) / 256, 256>>>(line_src, line_dst,                 // 1
                                      g2b_src, g2b_dst, b2g_src, b2g_dst);
    k_gather<<<GATH_BLOCKS, 256>>>(x_bus, x_gen);                         // 2
    k_fused<<<BUSB + GENB, 256, SMEM_FUSED>>>(x_bus, x_gen,               // 3
                                  Wsb[0], Wl[0], Wg2b[0], bsb[0],
                                  Wsg[0], Wb2g[0], bsg[0]);
    k_gather<<<GATH_BLOCKS, 256>>>(nullptr, nullptr);                     // 4 (ncu)
    k_fused<<<BUSB + GENB, 256, SMEM_FUSED>>>(nullptr, nullptr,           // 5
                                  Wsb[1], Wl[1], Wg2b[1], bsb[1],
                                  Wsg[1], Wb2g[1], bsg[1]);
    k_pool_all<<<300, 256>>>();                                           // 6
    k_head<<<1, 128>>>(W_h, b_h, W_o, b_o, (float*)d_out);                // 7
}